// round 2
// baseline (speedup 1.0000x reference)
#include <cuda_runtime.h>
#include <cstdint>
#include <cstddef>

#define BATCH 64
#define SEQT  512
#define DIN   256
#define HDIM  1024
#define DOUT  128
#define GRID  128

typedef unsigned long long u64;

// ---------------- scratch (device globals: allocation-free) ----------------
__device__ __align__(16) static float g_P[(size_t)BATCH * SEQT * HDIM]; // pre-activations
__device__ __align__(16) static float g_S[(size_t)BATCH * SEQT * HDIM]; // layer outputs / h
__device__ volatile unsigned g_flags[GRID];                             // barrier flags (zero-init)

// ---------------- packed f32x2 helpers ----------------
__device__ __forceinline__ u64 pk2(float lo, float hi) {
    u64 r; asm("mov.b64 %0, {%1, %2};" : "=l"(r) : "f"(lo), "f"(hi)); return r;
}
__device__ __forceinline__ void fma2(u64 &d, u64 a, u64 b) {
    asm("fma.rn.f32x2 %0, %1, %2, %0;" : "+l"(d) : "l"(a), "l"(b));
}
__device__ __forceinline__ u64 add2(u64 a, u64 b) {
    u64 r; asm("add.rn.f32x2 %0, %1, %2;" : "=l"(r) : "l"(a), "l"(b)); return r;
}
__device__ __forceinline__ float2 up2(u64 v) {
    float2 f; asm("mov.b64 {%0, %1}, %2;" : "=f"(f.x), "=f"(f.y) : "l"(v)); return f;
}

// ---------------- grid barrier (flag array, no atomics) ----------------
__device__ __forceinline__ void gsync(unsigned gen) {
    __syncthreads();
    if (threadIdx.x == 0) {
        __threadfence();                 // release prior global writes
        g_flags[blockIdx.x] = gen;       // volatile store
    }
    if (threadIdx.x < GRID) {
        while (g_flags[threadIdx.x] < gen) { }
    }
    __syncthreads();
}

// ============================================================================
// Projection GEMM: C[32768][1024] = A[32768][K] @ W[1024][K]^T + (bi + bh)
// grid 2048 (256 m-tiles x 8 n-tiles), 256 threads, 128x128 tile, 8x8/thread
// ============================================================================
__global__ void __launch_bounds__(256) proj_kernel(
    const float* __restrict__ A, const float* __restrict__ W,
    const float* __restrict__ bi, const float* __restrict__ bh,
    float* __restrict__ C, int K)
{
    __shared__ __align__(16) float sA[16 * 132];
    __shared__ __align__(16) float sB[16 * 132];

    const int tid = threadIdx.x;
    const int tm = blockIdx.x >> 3;   // 0..255
    const int tn = blockIdx.x & 7;    // 0..7
    const int ty = tid >> 4;          // 0..15 (m)
    const int tx = tid & 15;          // 0..15 (n)
    const int lr = tid >> 2;          // 0..63 load row
    const int lq = tid & 3;           // 0..3  load quad

    u64 acc[8][4];
    #pragma unroll
    for (int i = 0; i < 8; i++)
        #pragma unroll
        for (int j = 0; j < 4; j++) acc[i][j] = 0ull;

    const float* Ab = A + (size_t)(tm * 128) * K;
    const float* Wb = W + (size_t)(tn * 128) * K;

    for (int kc = 0; kc < K; kc += 16) {
        __syncthreads();
        #pragma unroll
        for (int p = 0; p < 2; p++) {
            const int rr = lr + p * 64;
            const float4 a4 = __ldg((const float4*)(Ab + (size_t)rr * K + kc + lq * 4));
            const float4 w4 = __ldg((const float4*)(Wb + (size_t)rr * K + kc + lq * 4));
            sA[(lq * 4 + 0) * 132 + rr] = a4.x;
            sA[(lq * 4 + 1) * 132 + rr] = a4.y;
            sA[(lq * 4 + 2) * 132 + rr] = a4.z;
            sA[(lq * 4 + 3) * 132 + rr] = a4.w;
            sB[(lq * 4 + 0) * 132 + rr] = w4.x;
            sB[(lq * 4 + 1) * 132 + rr] = w4.y;
            sB[(lq * 4 + 2) * 132 + rr] = w4.z;
            sB[(lq * 4 + 3) * 132 + rr] = w4.w;
        }
        __syncthreads();
        #pragma unroll
        for (int kk = 0; kk < 16; kk++) {
            const float4 a0 = *(const float4*)&sA[kk * 132 + ty * 4];
            const float4 a1 = *(const float4*)&sA[kk * 132 + 64 + ty * 4];
            const ulonglong2 bq0 = *(const ulonglong2*)&sB[kk * 132 + tx * 4];
            const ulonglong2 bq1 = *(const ulonglong2*)&sB[kk * 132 + 64 + tx * 4];
            const float am[8] = {a0.x, a0.y, a0.z, a0.w, a1.x, a1.y, a1.z, a1.w};
            #pragma unroll
            for (int i = 0; i < 8; i++) {
                const u64 ad = pk2(am[i], am[i]);
                fma2(acc[i][0], ad, bq0.x);
                fma2(acc[i][1], ad, bq0.y);
                fma2(acc[i][2], ad, bq1.x);
                fma2(acc[i][3], ad, bq1.y);
            }
        }
    }

    // epilogue: + (bi + bh), store
    const int n0 = tn * 128 + tx * 4;
    const int n1 = n0 + 64;
    float4 bia0, bia1;
    {
        const float4 i0 = __ldg((const float4*)(bi + n0));
        const float4 h0 = __ldg((const float4*)(bh + n0));
        const float4 i1 = __ldg((const float4*)(bi + n1));
        const float4 h1 = __ldg((const float4*)(bh + n1));
        bia0 = make_float4(i0.x + h0.x, i0.y + h0.y, i0.z + h0.z, i0.w + h0.w);
        bia1 = make_float4(i1.x + h1.x, i1.y + h1.y, i1.z + h1.z, i1.w + h1.w);
    }
    #pragma unroll
    for (int i = 0; i < 8; i++) {
        const int m = tm * 128 + (i < 4 ? ty * 4 + i : 64 + ty * 4 + (i - 4));
        const float2 c0 = up2(acc[i][0]), c1 = up2(acc[i][1]);
        const float2 c2 = up2(acc[i][2]), c3 = up2(acc[i][3]);
        *(float4*)(C + (size_t)m * HDIM + n0) =
            make_float4(c0.x + bia0.x, c0.y + bia0.y, c1.x + bia0.z, c1.y + bia0.w);
        *(float4*)(C + (size_t)m * HDIM + n1) =
            make_float4(c2.x + bia1.x, c2.y + bia1.y, c3.x + bia1.z, c3.y + bia1.w);
    }
}

// ============================================================================
// Recurrent scan: for t in [0,512): S[:,t,:] = relu(P[:,t,:] + S[:,t-1,:] @ Whh^T)
// Persistent: 128 CTAs x 256 thr. CTA tile = [16 b x 32 o]; Whh slice (transposed)
// resident in smem whole layer. 8-way k-split, [4b x 4o]/thread, f32x2 FMA.
// ============================================================================
// smem float offsets
#define SM_WT   0                       // wT[1024][32]
#define SM_H    (1024 * 32)             // hS[16][1028]  (pad 1028 -> conflict-free)
#define SM_RED  (SM_H + 16 * 1028)      // red[8][16][32]
#define SCAN_SMEM_BYTES ((SM_RED + 8 * 16 * 32) * 4)   // 213248 B

__global__ void __launch_bounds__(256) scan_kernel(
    const float* __restrict__ P, float* __restrict__ S,
    const float* __restrict__ Whh)
{
    extern __shared__ __align__(16) float sm[];
    float* wT  = sm + SM_WT;
    float* hS  = sm + SM_H;
    float* red = sm + SM_RED;

    const int tid = threadIdx.x;
    const int cta = blockIdx.x;
    const int b0 = (cta >> 5) * 16;     // batch block
    const int o0 = (cta & 31) * 32;     // output block
    const int b_t = tid & 3;            // 0..3  -> 4 batches each
    const int o_t = (tid >> 2) & 7;     // 0..7  -> 4 outputs each
    const int ks  = tid >> 5;           // 0..7  k-slice == warp id

    // Load Whh slice transposed: wT[k][j] = Whh[o0+j][k]   (once per layer)
    for (int i = tid; i < 8192; i += 256) {
        const int qq = i >> 5, j = i & 31;
        const float4 w4 = __ldg((const float4*)(Whh + (size_t)(o0 + j) * HDIM + qq * 4));
        wT[(qq * 4 + 0) * 32 + j] = w4.x;
        wT[(qq * 4 + 1) * 32 + j] = w4.y;
        wT[(qq * 4 + 2) * 32 + j] = w4.z;
        wT[(qq * 4 + 3) * 32 + j] = w4.w;
    }

    unsigned gen = g_flags[cta];        // persists across launches; uniform

    // Epilogue mapping: 2 outputs per thread
    const int pb = tid >> 4;                  // 0..15 batch
    const int po = (tid & 15) * 2;            // 0..30 even col
    const size_t prow = ((size_t)(b0 + pb) * SEQT) * HDIM + o0 + po;

    // t = 0: h = relu(pre)
    {
        const float2 p2 = *(const float2*)(P + prow);
        *(float2*)(S + prow) = make_float2(fmaxf(p2.x, 0.f), fmaxf(p2.y, 0.f));
    }
    gen++; gsync(gen);

    for (int t = 1; t < SEQT; t++) {
        // prefetch this thread's pre-activation pair
        const float2 p2 = __ldg((const float2*)(P + prow + (size_t)t * HDIM));

        // stage h_{t-1} rows [b0, b0+16) into smem (L2-coherent loads)
        const size_t tprev = (size_t)(t - 1) * HDIM;
        #pragma unroll
        for (int i = tid; i < 4096; i += 256) {
            const int bb = i >> 8, qq = i & 255;
            const float4 hv = __ldcg((const float4*)(S + ((size_t)(b0 + bb) * SEQT) * HDIM + tprev + qq * 4));
            *(float4*)&hS[bb * 1028 + qq * 4] = hv;
        }
        __syncthreads();

        // partial GEMM over this warp's k-slice
        u64 acc[4][2] = {{0ull,0ull},{0ull,0ull},{0ull,0ull},{0ull,0ull}};
        const int kbase = ks * 128;
        #pragma unroll 4
        for (int k = kbase; k < kbase + 128; k += 4) {
            const float4 h0 = *(const float4*)&hS[(b_t * 4 + 0) * 1028 + k];
            const float4 h1 = *(const float4*)&hS[(b_t * 4 + 1) * 1028 + k];
            const float4 h2 = *(const float4*)&hS[(b_t * 4 + 2) * 1028 + k];
            const float4 h3 = *(const float4*)&hS[(b_t * 4 + 3) * 1028 + k];
            const float ha[4][4] = {{h0.x, h0.y, h0.z, h0.w},
                                    {h1.x, h1.y, h1.z, h1.w},
                                    {h2.x, h2.y, h2.z, h2.w},
                                    {h3.x, h3.y, h3.z, h3.w}};
            #pragma unroll
            for (int kk = 0; kk < 4; kk++) {
                const ulonglong2 wv = *(const ulonglong2*)&wT[(k + kk) * 32 + o_t * 4];
                #pragma unroll
                for (int i = 0; i < 4; i++) {
                    const u64 hd = pk2(ha[i][kk], ha[i][kk]);
                    fma2(acc[i][0], hd, wv.x);
                    fma2(acc[i][1], hd, wv.y);
                }
            }
        }

        // stash k-slice partials
        #pragma unroll
        for (int i = 0; i < 4; i++) {
            u64* dst = (u64*)&red[ks * 512 + (b_t * 4 + i) * 32 + o_t * 4];
            dst[0] = acc[i][0];
            dst[1] = acc[i][1];
        }
        __syncthreads();

        // reduce 8 slices for this thread's 2 outputs, fuse bias(pre)+relu, store h_t
        u64 s2 = *(const u64*)&red[pb * 32 + po];
        #pragma unroll
        for (int k8 = 1; k8 < 8; k8++)
            s2 = add2(s2, *(const u64*)&red[k8 * 512 + pb * 32 + po]);
        const float2 sv = up2(s2);
        *(float2*)(S + prow + (size_t)t * HDIM) =
            make_float2(fmaxf(sv.x + p2.x, 0.f), fmaxf(sv.y + p2.y, 0.f));

        gen++; gsync(gen);
    }
}

// ============================================================================
// FC: out[64][128] = S[:, T-1, :] @ fc_w^T + fc_b
// ============================================================================
__global__ void __launch_bounds__(128) fc_kernel(
    const float* __restrict__ S, const float* __restrict__ fw,
    const float* __restrict__ fb, float* __restrict__ out)
{
    __shared__ __align__(16) float sx[HDIM];
    const int b = blockIdx.x, tid = threadIdx.x;
    const float* xrow = S + ((size_t)b * SEQT + (SEQT - 1)) * HDIM;
    for (int i = tid; i < HDIM / 4; i += 128)
        *(float4*)&sx[i * 4] = __ldcg((const float4*)(xrow + i * 4));
    __syncthreads();
    float acc = 0.f;
    const float* wrow = fw + (size_t)tid * HDIM;
    #pragma unroll 8
    for (int q = 0; q < HDIM / 4; q++) {
        const float4 w4 = __ldg((const float4*)(wrow + q * 4));
        const float4 x4 = *(const float4*)&sx[q * 4];
        acc += w4.x * x4.x + w4.y * x4.y + w4.z * x4.z + w4.w * x4.w;
    }
    out[(size_t)b * DOUT + tid] = acc + __ldg(fb + tid);
}

// ============================================================================
extern "C" void kernel_launch(void* const* d_in, const int* in_sizes, int n_in,
                              void* d_out, int out_size)
{
    const float* x    = (const float*)d_in[0];   // [64,512,256]
    const float* wih0 = (const float*)d_in[1];   // [1024,256]
    const float* wihr = (const float*)d_in[2];   // [2,1024,1024]
    const float* whh  = (const float*)d_in[3];   // [3,1024,1024]
    const float* bih  = (const float*)d_in[4];   // [3,1024]
    const float* bhh  = (const float*)d_in[5];   // [3,1024]
    const float* fcw  = (const float*)d_in[6];   // [128,1024]
    const float* fcb  = (const float*)d_in[7];   // [128]
    float* out = (float*)d_out;                  // [64,128]

    cudaFuncSetAttribute(scan_kernel, cudaFuncAttributeMaxDynamicSharedMemorySize,
                         SCAN_SMEM_BYTES);

    void *pP = nullptr, *pS = nullptr;
    cudaGetSymbolAddress(&pP, g_P);
    cudaGetSymbolAddress(&pS, g_S);
    float* P  = (float*)pP;
    float* Sq = (float*)pS;

    // layer 0
    proj_kernel<<<2048, 256>>>(x, wih0, bih, bhh, P, DIN);
    scan_kernel<<<GRID, 256, SCAN_SMEM_BYTES>>>(P, Sq, whh);
    // layer 1
    proj_kernel<<<2048, 256>>>(Sq, wihr, bih + HDIM, bhh + HDIM, P, HDIM);
    scan_kernel<<<GRID, 256, SCAN_SMEM_BYTES>>>(P, Sq, whh + (size_t)HDIM * HDIM);
    // layer 2
    proj_kernel<<<2048, 256>>>(Sq, wihr + (size_t)HDIM * HDIM, bih + 2 * HDIM, bhh + 2 * HDIM, P, HDIM);
    scan_kernel<<<GRID, 256, SCAN_SMEM_BYTES>>>(P, Sq, whh + 2 * (size_t)HDIM * HDIM);
    // head
    fc_kernel<<<BATCH, 128>>>(Sq, fcw, fcb, out);
}

// round 3
// speedup vs baseline: 1.2443x; 1.2443x over previous
#include <cuda_runtime.h>
#include <cstdint>
#include <cstddef>

#define BATCH 64
#define SEQT  512
#define DIN   256
#define HDIM  1024
#define DOUT  128
#define GRID  128

typedef unsigned long long u64;

// ---------------- scratch (device globals: allocation-free) ----------------
__device__ __align__(16) static float g_P[(size_t)BATCH * SEQT * HDIM]; // pre-activations
__device__ __align__(16) static float g_S[(size_t)BATCH * SEQT * HDIM]; // layer outputs / h
__device__ volatile unsigned g_flags[GRID];                             // barrier flags (zero-init)

// ---------------- packed f32x2 helpers ----------------
__device__ __forceinline__ void fma2(u64 &d, u64 a, u64 b) {
    asm("fma.rn.f32x2 %0, %1, %2, %0;" : "+l"(d) : "l"(a), "l"(b));
}
__device__ __forceinline__ u64 add2(u64 a, u64 b) {
    u64 r; asm("add.rn.f32x2 %0, %1, %2;" : "=l"(r) : "l"(a), "l"(b)); return r;
}
__device__ __forceinline__ float2 up2(u64 v) {
    float2 f; asm("mov.b64 {%0, %1}, %2;" : "=f"(f.x), "=f"(f.y) : "l"(v)); return f;
}

__device__ __forceinline__ uint32_t smem_u32(const void* p) {
    uint32_t a;
    asm("{ .reg .u64 t; cvta.to.shared.u64 t, %1; cvt.u32.u64 %0, t; }" : "=r"(a) : "l"(p));
    return a;
}
__device__ __forceinline__ void cpasync16(uint32_t dst, const void* src) {
    asm volatile("cp.async.cg.shared.global [%0], [%1], 16;" :: "r"(dst), "l"(src));
}
__device__ __forceinline__ void cpasync_commit_wait() {
    asm volatile("cp.async.commit_group;");
    asm volatile("cp.async.wait_group 0;" ::: "memory");
}

// ---------------- grid barrier (flag array, no atomics) ----------------
__device__ __forceinline__ void gsync(unsigned gen) {
    __syncthreads();
    if (threadIdx.x == 0) {
        __threadfence();                 // release prior global writes
        g_flags[blockIdx.x] = gen;       // volatile store
    }
    if (threadIdx.x < GRID) {
        while (g_flags[threadIdx.x] < gen) { }
    }
    __syncthreads();
}

// ============================================================================
// Projection GEMM: C[32768][1024] = A[32768][K] @ W[1024][K]^T + (bi + bh)
// grid 2048 (256 m-tiles x 8 n-tiles), 256 threads, 128x128 tile, 8x8/thread
// ============================================================================
__global__ void __launch_bounds__(256, 2) proj_kernel(
    const float* __restrict__ A, const float* __restrict__ W,
    const float* __restrict__ bi, const float* __restrict__ bh,
    float* __restrict__ C, int K)
{
    __shared__ __align__(16) float sA[16 * 132];
    __shared__ __align__(16) float sB[16 * 132];

    const int tid = threadIdx.x;
    const int tm = blockIdx.x >> 3;   // 0..255
    const int tn = blockIdx.x & 7;    // 0..7
    const int ty = tid >> 4;          // 0..15 (m)
    const int tx = tid & 15;          // 0..15 (n)
    const int lr = tid >> 2;          // 0..63 load row
    const int lq = tid & 3;           // 0..3  load quad

    u64 acc[8][4];
    #pragma unroll
    for (int i = 0; i < 8; i++)
        #pragma unroll
        for (int j = 0; j < 4; j++) acc[i][j] = 0ull;

    const float* Ab = A + (size_t)(tm * 128) * K;
    const float* Wb = W + (size_t)(tn * 128) * K;

    for (int kc = 0; kc < K; kc += 16) {
        __syncthreads();
        #pragma unroll
        for (int p = 0; p < 2; p++) {
            const int rr = lr + p * 64;
            const float4 a4 = __ldg((const float4*)(Ab + (size_t)rr * K + kc + lq * 4));
            const float4 w4 = __ldg((const float4*)(Wb + (size_t)rr * K + kc + lq * 4));
            sA[(lq * 4 + 0) * 132 + rr] = a4.x;
            sA[(lq * 4 + 1) * 132 + rr] = a4.y;
            sA[(lq * 4 + 2) * 132 + rr] = a4.z;
            sA[(lq * 4 + 3) * 132 + rr] = a4.w;
            sB[(lq * 4 + 0) * 132 + rr] = w4.x;
            sB[(lq * 4 + 1) * 132 + rr] = w4.y;
            sB[(lq * 4 + 2) * 132 + rr] = w4.z;
            sB[(lq * 4 + 3) * 132 + rr] = w4.w;
        }
        __syncthreads();
        #pragma unroll
        for (int kk = 0; kk < 16; kk++) {
            const float4 a0 = *(const float4*)&sA[kk * 132 + ty * 4];
            const float4 a1 = *(const float4*)&sA[kk * 132 + 64 + ty * 4];
            const ulonglong2 bq0 = *(const ulonglong2*)&sB[kk * 132 + tx * 4];
            const ulonglong2 bq1 = *(const ulonglong2*)&sB[kk * 132 + 64 + tx * 4];
            const float am[8] = {a0.x, a0.y, a0.z, a0.w, a1.x, a1.y, a1.z, a1.w};
            #pragma unroll
            for (int i = 0; i < 8; i++) {
                u64 ad;
                asm("mov.b64 %0, {%1, %1};" : "=l"(ad) : "f"(am[i]));
                fma2(acc[i][0], ad, bq0.x);
                fma2(acc[i][1], ad, bq0.y);
                fma2(acc[i][2], ad, bq1.x);
                fma2(acc[i][3], ad, bq1.y);
            }
        }
    }

    // epilogue: + (bi + bh), store
    const int n0 = tn * 128 + tx * 4;
    const int n1 = n0 + 64;
    float4 bia0, bia1;
    {
        const float4 i0 = __ldg((const float4*)(bi + n0));
        const float4 h0 = __ldg((const float4*)(bh + n0));
        const float4 i1 = __ldg((const float4*)(bi + n1));
        const float4 h1 = __ldg((const float4*)(bh + n1));
        bia0 = make_float4(i0.x + h0.x, i0.y + h0.y, i0.z + h0.z, i0.w + h0.w);
        bia1 = make_float4(i1.x + h1.x, i1.y + h1.y, i1.z + h1.z, i1.w + h1.w);
    }
    #pragma unroll
    for (int i = 0; i < 8; i++) {
        const int m = tm * 128 + (i < 4 ? ty * 4 + i : 64 + ty * 4 + (i - 4));
        const float2 c0 = up2(acc[i][0]), c1 = up2(acc[i][1]);
        const float2 c2 = up2(acc[i][2]), c3 = up2(acc[i][3]);
        *(float4*)(C + (size_t)m * HDIM + n0) =
            make_float4(c0.x + bia0.x, c0.y + bia0.y, c1.x + bia0.z, c1.y + bia0.w);
        *(float4*)(C + (size_t)m * HDIM + n1) =
            make_float4(c2.x + bia1.x, c2.y + bia1.y, c3.x + bia1.z, c3.y + bia1.w);
    }
}

// ============================================================================
// Recurrent scan: for t in [0,512): S[:,t,:] = relu(P[:,t,:] + S[:,t-1,:] @ Whh^T)
// Persistent: 128 CTAs x 256 thr, 1 CTA/SM. CTA tile = [16b x 32o].
// Whh slice resident in smem (k-major, NO transpose). K-PACKED f32x2:
// acc u64 holds (even-k, odd-k) partial sums -> zero pack MOVs.
// Thread = [4b x 4o x 128k]; 8-way k-split across warps; smem reduce.
// ============================================================================
// smem float offsets (row stride 1028 floats: +16B pad)
#define SM_W   0                          // wS[32][1028]  (o rows, k-major)
#define SM_H   (32 * 1028)                // hS[16][1028]
#define SM_R   (SM_H + 16 * 1028)         // red: u64[8][16][32]
#define SCAN_SMEM_BYTES ((SM_R + 8 * 16 * 32 * 2) * 4)   // 230,144 B

__global__ void __launch_bounds__(256, 1) scan_kernel(
    const float* __restrict__ P, float* __restrict__ S,
    const float* __restrict__ Whh)
{
    extern __shared__ __align__(16) float sm[];
    float* wS = sm + SM_W;
    float* hS = sm + SM_H;
    u64*   red = (u64*)(sm + SM_R);

    const int tid = threadIdx.x;
    const int cta = blockIdx.x;
    const int b0 = (cta >> 5) * 16;     // batch block
    const int o0 = (cta & 31) * 32;     // output block
    const int b_t = tid & 3;            // row-within-group (b = i*4 + b_t)
    const int o_t = (tid >> 2) & 7;     // row-within-group (o = j*8 + o_t)
    const int ks  = tid >> 5;           // warp id = k-slice 0..7

    // Load Whh slice (k-major, no transpose): wS[j][k] = Whh[o0+j][k]
    for (int i = tid; i < 8192; i += 256) {
        const int j = i >> 8, q = i & 255;
        const float4 w4 = __ldg((const float4*)(Whh + (size_t)(o0 + j) * HDIM + q * 4));
        *(float4*)&wS[j * 1028 + q * 4] = w4;
    }

    unsigned gen = g_flags[cta];        // persists across launches; uniform

    // Epilogue mapping: 2 adjacent outputs per thread
    const int pb = tid >> 4;                  // 0..15 batch
    const int po = (tid & 15) * 2;            // 0..30 even col
    const size_t prow = ((size_t)(b0 + pb) * SEQT) * HDIM + o0 + po;

    // t = 0: h = relu(pre)
    {
        const float2 p2 = *(const float2*)(P + prow);
        *(float2*)(S + prow) = make_float2(fmaxf(p2.x, 0.f), fmaxf(p2.y, 0.f));
    }
    gen++; gsync(gen);

    const uint32_t hS_a = smem_u32(hS);
    const float* Sb = S + (size_t)b0 * SEQT * HDIM;
    const int kb = ks * 128;

    for (int t = 1; t < SEQT; t++) {
        // prefetch this thread's pre-activation pair (L1 ok, P immutable)
        const float2 p2 = __ldg((const float2*)(P + prow + (size_t)t * HDIM));

        // stage h_{t-1}[b0..b0+16) into smem via cp.async (.cg = L2-coherent)
        {
            const size_t tprev = (size_t)(t - 1) * HDIM;
            #pragma unroll
            for (int p = 0; p < 16; p++) {
                const int i = p * 256 + tid;
                const int bb = i >> 8, qq = i & 255;
                cpasync16(hS_a + (uint32_t)(bb * 1028 + qq * 4) * 4,
                          Sb + (size_t)bb * SEQT * HDIM + tprev + qq * 4);
            }
            cpasync_commit_wait();
        }
        __syncthreads();

        // k-packed partial GEMM over this warp's 128-k slice
        u64 acc[4][4];
        #pragma unroll
        for (int i = 0; i < 4; i++)
            #pragma unroll
            for (int j = 0; j < 4; j++) acc[i][j] = 0ull;

        #pragma unroll 2
        for (int kq = 0; kq < 128; kq += 4) {
            float4 hv[4], wv[4];
            #pragma unroll
            for (int i = 0; i < 4; i++)
                hv[i] = *(const float4*)&hS[(i * 4 + b_t) * 1028 + kb + kq];
            #pragma unroll
            for (int j = 0; j < 4; j++)
                wv[j] = *(const float4*)&wS[(j * 8 + o_t) * 1028 + kb + kq];
            // lo pairs (k, k+1)
            #pragma unroll
            for (int i = 0; i < 4; i++)
                #pragma unroll
                for (int j = 0; j < 4; j++)
                    fma2(acc[i][j], ((const u64*)&hv[i])[0], ((const u64*)&wv[j])[0]);
            // hi pairs (k+2, k+3)
            #pragma unroll
            for (int i = 0; i < 4; i++)
                #pragma unroll
                for (int j = 0; j < 4; j++)
                    fma2(acc[i][j], ((const u64*)&hv[i])[1], ((const u64*)&wv[j])[1]);
        }

        // stash k-slice partials: red[ks][b][o]
        #pragma unroll
        for (int i = 0; i < 4; i++)
            #pragma unroll
            for (int j = 0; j < 4; j++)
                red[ks * 512 + (i * 4 + b_t) * 32 + (j * 8 + o_t)] = acc[i][j];
        __syncthreads();

        // reduce 8 slices, fold (even,odd) halves, fuse pre+relu, store h_t
        {
            ulonglong2 v = *(const ulonglong2*)&red[pb * 32 + po];
            u64 s0 = v.x, s1 = v.y;
            #pragma unroll
            for (int w8 = 1; w8 < 8; w8++) {
                const ulonglong2 r = *(const ulonglong2*)&red[w8 * 512 + pb * 32 + po];
                s0 = add2(s0, r.x);
                s1 = add2(s1, r.y);
            }
            const float2 a0 = up2(s0), a1 = up2(s1);
            *(float2*)(S + prow + (size_t)t * HDIM) =
                make_float2(fmaxf(a0.x + a0.y + p2.x, 0.f),
                            fmaxf(a1.x + a1.y + p2.y, 0.f));
        }
        gen++; gsync(gen);
    }
}

// ============================================================================
// FC: out[64][128] = S[:, T-1, :] @ fc_w^T + fc_b
// ============================================================================
__global__ void __launch_bounds__(128) fc_kernel(
    const float* __restrict__ S, const float* __restrict__ fw,
    const float* __restrict__ fb, float* __restrict__ out)
{
    __shared__ __align__(16) float sx[HDIM];
    const int b = blockIdx.x, tid = threadIdx.x;
    const float* xrow = S + ((size_t)b * SEQT + (SEQT - 1)) * HDIM;
    for (int i = tid; i < HDIM / 4; i += 128)
        *(float4*)&sx[i * 4] = __ldcg((const float4*)(xrow + i * 4));
    __syncthreads();
    float acc = 0.f;
    const float* wrow = fw + (size_t)tid * HDIM;
    #pragma unroll 8
    for (int q = 0; q < HDIM / 4; q++) {
        const float4 w4 = __ldg((const float4*)(wrow + q * 4));
        const float4 x4 = *(const float4*)&sx[q * 4];
        acc += w4.x * x4.x + w4.y * x4.y + w4.z * x4.z + w4.w * x4.w;
    }
    out[(size_t)b * DOUT + tid] = acc + __ldg(fb + tid);
}

// ============================================================================
extern "C" void kernel_launch(void* const* d_in, const int* in_sizes, int n_in,
                              void* d_out, int out_size)
{
    const float* x    = (const float*)d_in[0];   // [64,512,256]
    const float* wih0 = (const float*)d_in[1];   // [1024,256]
    const float* wihr = (const float*)d_in[2];   // [2,1024,1024]
    const float* whh  = (const float*)d_in[3];   // [3,1024,1024]
    const float* bih  = (const float*)d_in[4];   // [3,1024]
    const float* bhh  = (const float*)d_in[5];   // [3,1024]
    const float* fcw  = (const float*)d_in[6];   // [128,1024]
    const float* fcb  = (const float*)d_in[7];   // [128]
    float* out = (float*)d_out;                  // [64,128]

    cudaFuncSetAttribute(scan_kernel, cudaFuncAttributeMaxDynamicSharedMemorySize,
                         SCAN_SMEM_BYTES);

    void *pP = nullptr, *pS = nullptr;
    cudaGetSymbolAddress(&pP, g_P);
    cudaGetSymbolAddress(&pS, g_S);
    float* P  = (float*)pP;
    float* Sq = (float*)pS;

    // layer 0
    proj_kernel<<<2048, 256>>>(x, wih0, bih, bhh, P, DIN);
    scan_kernel<<<GRID, 256, SCAN_SMEM_BYTES>>>(P, Sq, whh);
    // layer 1
    proj_kernel<<<2048, 256>>>(Sq, wihr, bih + HDIM, bhh + HDIM, P, HDIM);
    scan_kernel<<<GRID, 256, SCAN_SMEM_BYTES>>>(P, Sq, whh + (size_t)HDIM * HDIM);
    // layer 2
    proj_kernel<<<2048, 256>>>(Sq, wihr + (size_t)HDIM * HDIM, bih + 2 * HDIM, bhh + 2 * HDIM, P, HDIM);
    scan_kernel<<<GRID, 256, SCAN_SMEM_BYTES>>>(P, Sq, whh + 2 * (size_t)HDIM * HDIM);
    // head
    fc_kernel<<<BATCH, 128>>>(Sq, fcw, fcb, out);
}